// round 13
// baseline (speedup 1.0000x reference)
#include <cuda_runtime.h>

// AbstractionLayer: B=524288, I=12, R=6, J=2, L=2, V=4
// R13 = R8 (best: 2 elems/thread lane-packed, features register-resident,
// one (r,j) per sweep) + wave-quantization fix: grid=2048 CTAs over 148 SMs
// = 13.84 CTAs/SM; at 6 resident -> 3 generations (last 31% full, ~23%
// idle). i-loop unroll 6 halves live ex2 staging temps so regs drop ~80 ->
// ~72 NATURALLY, letting lb(128,7) give 7 resident blocks -> 1.98 ~= 2
// clean generations. 6 independent ex2 chains still cover MUFU rt=8.
// Softmax max-pass removed (logits bounded); log2e folded into coefs (raw
// ex2.approx); head*body pre-fused; rcp.approx (tol 1e-3).

#define NI 12
#define NR 6
#define NJ 2
#define NL 2
#define NV 4
#define NRJ 12
#define NT 128
#define LOG2E 1.4426950408889634f

typedef unsigned long long u64;

__device__ __forceinline__ u64 pk2(float lo, float hi) {
    u64 r; asm("mov.b64 %0, {%1,%2};" : "=l"(r) : "f"(lo), "f"(hi)); return r;
}
__device__ __forceinline__ void upk2(u64 v, float& lo, float& hi) {
    asm("mov.b64 {%0,%1}, %2;" : "=f"(lo), "=f"(hi) : "l"(v));
}
__device__ __forceinline__ u64 fma2(u64 a, u64 b, u64 c) {
    u64 d; asm("fma.rn.f32x2 %0, %1, %2, %3;" : "=l"(d) : "l"(a), "l"(b), "l"(c)); return d;
}
__device__ __forceinline__ u64 mul2(u64 a, u64 b) {
    u64 d; asm("mul.rn.f32x2 %0, %1, %2;" : "=l"(d) : "l"(a), "l"(b)); return d;
}
__device__ __forceinline__ u64 add2(u64 a, u64 b) {
    u64 d; asm("add.rn.f32x2 %0, %1, %2;" : "=l"(d) : "l"(a), "l"(b)); return d;
}
__device__ __forceinline__ float ex2a(float x) {
    float r; asm("ex2.approx.ftz.f32 %0, %1;" : "=f"(r) : "f"(x)); return r;
}
__device__ __forceinline__ float rcpa(float x) {
    float r; asm("rcp.approx.ftz.f32 %0, %1;" : "=f"(r) : "f"(x)); return r;
}

__global__ __launch_bounds__(NT, 7)
void abstraction_layer_kernel(
    const float* __restrict__ feat,       // [B, I, L]
    const float* __restrict__ templates,  // [R, J, L]
    const float* __restrict__ gammas,     // [R, J, L]
    const float* __restrict__ body_W,     // [R, J, V, L]
    const float* __restrict__ body_b,     // [R, J, V]
    const float* __restrict__ head_W,     // [R, L, V]
    const float* __restrict__ head_b,     // [R, L]
    float* __restrict__ out,              // [B, R, L]
    int B)
{
    __shared__ u64 s_coef[NRJ][4];       // log2e-scaled logit coefs, lane-dup
    __shared__ u64 s_M[NRJ][4];          // fused head*body, lane-dup
    __shared__ u64 s_c[NR * NL];         // fused bias, lane-dup

    const int tid = threadIdx.x;

    // ---- one-time parameter fusion (disjoint thread ranges) ----
    if (tid < NRJ) {
        const int r = tid >> 1, j = tid & 1;
        #pragma unroll
        for (int l = 0; l < NL; l++) {
            float g = gammas[(r * NJ + j) * NL + l];
            g = fminf(fmaxf(g, 0.0f), 1.0f);
            const float w = 1.0f - g;
            const float t = templates[(r * NJ + j) * NL + l];
            const float clin  = 2.0f * w * t * LOG2E;
            const float cquad = -w * LOG2E;
            s_coef[tid][l]     = pk2(clin, clin);
            s_coef[tid][2 + l] = pk2(cquad, cquad);
        }
    } else if (tid >= 16 && tid < 16 + 48) {
        const int idx = tid - 16;
        const int l2 = idx & 1, j = (idx >> 1) & 1, l = (idx >> 2) & 1, r = idx >> 3;
        float acc = 0.0f;
        #pragma unroll
        for (int v = 0; v < NV; v++)
            acc += head_W[(r * NL + l) * NV + v] *
                   body_W[((r * NJ + j) * NV + v) * NL + l2];
        s_M[r * NJ + j][l * 2 + l2] = pk2(acc, acc);
    } else if (tid >= 64 && tid < 64 + NR * NL) {
        const int idx = tid - 64;
        const int r = idx >> 1, l = idx & 1;
        float acc = head_b[r * NL + l];
        #pragma unroll
        for (int v = 0; v < NV; v++)
            acc += head_W[(r * NL + l) * NV + v] *
                   (body_b[(r * NJ + 0) * NV + v] + body_b[(r * NJ + 1) * NV + v]);
        s_c[idx] = pk2(acc, acc);
    }
    __syncthreads();

    const int half = B >> 1;
    const int t = blockIdx.x * blockDim.x + tid;
    if (t >= half) return;

    // ---- load features of elements (t, t+half) into REGISTERS, packed ----
    u64 F0[NI], F1[NI];
    {
        const float4* fa = reinterpret_cast<const float4*>(feat + (size_t)t * (NI * NL));
        const float4* fb = reinterpret_cast<const float4*>(feat + (size_t)(t + half) * (NI * NL));
        #pragma unroll
        for (int k = 0; k < 6; k++) {
            const float4 a = fa[k];
            const float4 b = fb[k];
            F0[2 * k]     = pk2(a.x, b.x); F1[2 * k]     = pk2(a.y, b.y);
            F0[2 * k + 1] = pk2(a.z, b.z); F1[2 * k + 1] = pk2(a.w, b.w);
        }
    }

    const size_t base  = (size_t)t * (NR * NL);
    const size_t delta = (size_t)half * (NR * NL);

    // ---- 12 sweeps, one (r,j) each; features stay in registers ----
    #pragma unroll 1
    for (int r = 0; r < NR; r++) {
        u64 A0 = s_c[2 * r + 0];
        u64 A1 = s_c[2 * r + 1];

        #pragma unroll 1
        for (int j = 0; j < NJ; j++) {
            const int rj = 2 * r + j;
            const u64 c0 = s_coef[rj][0], c1 = s_coef[rj][1];
            const u64 c2 = s_coef[rj][2], c3 = s_coef[rj][3];

            u64 se = 0ULL, n0 = 0ULL, n1 = 0ULL;
            #pragma unroll 6
            for (int i = 0; i < NI; i++) {
                const u64 t1 = fma2(c2, F0[i], c0);   // f0*(c0+c2*f0)
                const u64 t2 = fma2(c3, F1[i], c1);   // + f1*(c1+c3*f1)
                const u64 lg = fma2(F0[i], t1, mul2(F1[i], t2));
                float llo, lhi; upk2(lg, llo, lhi);
                const u64 e = pk2(ex2a(llo), ex2a(lhi));
                se = add2(se, e);
                n0 = fma2(e, F0[i], n0);
                n1 = fma2(e, F1[i], n1);
            }

            float slo, shi; upk2(se, slo, shi);
            const u64 rinv = pk2(rcpa(slo), rcpa(shi));
            const u64 s0 = mul2(n0, rinv);
            const u64 s1 = mul2(n1, rinv);

            A0 = fma2(s_M[rj][0], s0, fma2(s_M[rj][1], s1, A0));
            A1 = fma2(s_M[rj][2], s0, fma2(s_M[rj][3], s1, A1));
        }

        float x0, x1, y0, y1;
        upk2(A0, x0, x1);
        upk2(A1, y0, y1);
        *reinterpret_cast<float2*>(out + base + r * 2)         = make_float2(x0, y0);
        *reinterpret_cast<float2*>(out + base + delta + r * 2) = make_float2(x1, y1);
    }
}

extern "C" void kernel_launch(void* const* d_in, const int* in_sizes, int n_in,
                              void* d_out, int out_size) {
    const float* feat      = (const float*)d_in[0];
    const float* templates = (const float*)d_in[1];
    const float* gammas    = (const float*)d_in[2];
    const float* body_W    = (const float*)d_in[3];
    const float* body_b    = (const float*)d_in[4];
    const float* head_W    = (const float*)d_in[5];
    const float* head_b    = (const float*)d_in[6];
    float* out = (float*)d_out;

    const int B = in_sizes[0] / (NI * NL);
    const int half = B >> 1;
    const int blocks = (half + NT - 1) / NT;
    abstraction_layer_kernel<<<blocks, NT>>>(
        feat, templates, gammas, body_W, body_b, head_W, head_b, out, B);
}

// round 14
// speedup vs baseline: 1.0307x; 1.0307x over previous
#include <cuda_runtime.h>

// AbstractionLayer: B=524288, I=12, R=6, J=2, L=2, V=4
// R14 = R8 body (best: 2 elems/thread lane-packed f32x2, features
// register-resident, one (r,j) per sweep, 80 regs natural) wrapped in a
// PERSISTENT grid-stride loop. grid = numSMs*6 = exactly one resident wave;
// each thread handles ~2.3 pairs. Kills the 3-wave quantization of the
// 2048-CTA launch (last wave ran at 1-2 blocks/SM): per-SM work is now
// exactly uniform, tail = one low-occupancy iteration on all SMs at once.
// Softmax max-pass removed (logits bounded); log2e folded into coefs (raw
// ex2.approx); head*body pre-fused; rcp.approx (tol 1e-3).

#define NI 12
#define NR 6
#define NJ 2
#define NL 2
#define NV 4
#define NRJ 12
#define NT 128
#define LOG2E 1.4426950408889634f

typedef unsigned long long u64;

__device__ __forceinline__ u64 pk2(float lo, float hi) {
    u64 r; asm("mov.b64 %0, {%1,%2};" : "=l"(r) : "f"(lo), "f"(hi)); return r;
}
__device__ __forceinline__ void upk2(u64 v, float& lo, float& hi) {
    asm("mov.b64 {%0,%1}, %2;" : "=f"(lo), "=f"(hi) : "l"(v));
}
__device__ __forceinline__ u64 fma2(u64 a, u64 b, u64 c) {
    u64 d; asm("fma.rn.f32x2 %0, %1, %2, %3;" : "=l"(d) : "l"(a), "l"(b), "l"(c)); return d;
}
__device__ __forceinline__ u64 mul2(u64 a, u64 b) {
    u64 d; asm("mul.rn.f32x2 %0, %1, %2;" : "=l"(d) : "l"(a), "l"(b)); return d;
}
__device__ __forceinline__ u64 add2(u64 a, u64 b) {
    u64 d; asm("add.rn.f32x2 %0, %1, %2;" : "=l"(d) : "l"(a), "l"(b)); return d;
}
__device__ __forceinline__ float ex2a(float x) {
    float r; asm("ex2.approx.ftz.f32 %0, %1;" : "=f"(r) : "f"(x)); return r;
}
__device__ __forceinline__ float rcpa(float x) {
    float r; asm("rcp.approx.ftz.f32 %0, %1;" : "=f"(r) : "f"(x)); return r;
}

__global__ __launch_bounds__(NT, 6)
void abstraction_layer_kernel(
    const float* __restrict__ feat,       // [B, I, L]
    const float* __restrict__ templates,  // [R, J, L]
    const float* __restrict__ gammas,     // [R, J, L]
    const float* __restrict__ body_W,     // [R, J, V, L]
    const float* __restrict__ body_b,     // [R, J, V]
    const float* __restrict__ head_W,     // [R, L, V]
    const float* __restrict__ head_b,     // [R, L]
    float* __restrict__ out,              // [B, R, L]
    int B)
{
    __shared__ u64 s_coef[NRJ][4];       // log2e-scaled logit coefs, lane-dup
    __shared__ u64 s_M[NRJ][4];          // fused head*body, lane-dup
    __shared__ u64 s_c[NR * NL];         // fused bias, lane-dup

    const int tid = threadIdx.x;

    // ---- one-time parameter fusion (disjoint thread ranges) ----
    if (tid < NRJ) {
        const int r = tid >> 1, j = tid & 1;
        #pragma unroll
        for (int l = 0; l < NL; l++) {
            float g = gammas[(r * NJ + j) * NL + l];
            g = fminf(fmaxf(g, 0.0f), 1.0f);
            const float w = 1.0f - g;
            const float t = templates[(r * NJ + j) * NL + l];
            const float clin  = 2.0f * w * t * LOG2E;
            const float cquad = -w * LOG2E;
            s_coef[tid][l]     = pk2(clin, clin);
            s_coef[tid][2 + l] = pk2(cquad, cquad);
        }
    } else if (tid >= 16 && tid < 16 + 48) {
        const int idx = tid - 16;
        const int l2 = idx & 1, j = (idx >> 1) & 1, l = (idx >> 2) & 1, r = idx >> 3;
        float acc = 0.0f;
        #pragma unroll
        for (int v = 0; v < NV; v++)
            acc += head_W[(r * NL + l) * NV + v] *
                   body_W[((r * NJ + j) * NV + v) * NL + l2];
        s_M[r * NJ + j][l * 2 + l2] = pk2(acc, acc);
    } else if (tid >= 64 && tid < 64 + NR * NL) {
        const int idx = tid - 64;
        const int r = idx >> 1, l = idx & 1;
        float acc = head_b[r * NL + l];
        #pragma unroll
        for (int v = 0; v < NV; v++)
            acc += head_W[(r * NL + l) * NV + v] *
                   (body_b[(r * NJ + 0) * NV + v] + body_b[(r * NJ + 1) * NV + v]);
        s_c[idx] = pk2(acc, acc);
    }
    __syncthreads();

    const int half   = B >> 1;
    const int stride = gridDim.x * blockDim.x;
    const size_t delta = (size_t)half * (NR * NL);

    // ---- persistent grid-stride loop over element pairs ----
    #pragma unroll 1
    for (int t = blockIdx.x * blockDim.x + tid; t < half; t += stride) {

        // load features of elements (t, t+half) into registers, packed
        u64 F0[NI], F1[NI];
        {
            const float4* fa = reinterpret_cast<const float4*>(feat + (size_t)t * (NI * NL));
            const float4* fb = reinterpret_cast<const float4*>(feat + (size_t)(t + half) * (NI * NL));
            #pragma unroll
            for (int k = 0; k < 6; k++) {
                const float4 a = fa[k];
                const float4 b = fb[k];
                F0[2 * k]     = pk2(a.x, b.x); F1[2 * k]     = pk2(a.y, b.y);
                F0[2 * k + 1] = pk2(a.z, b.z); F1[2 * k + 1] = pk2(a.w, b.w);
            }
        }

        const size_t base = (size_t)t * (NR * NL);

        // 12 sweeps, one (r,j) each; features stay in registers
        #pragma unroll 1
        for (int r = 0; r < NR; r++) {
            u64 A0 = s_c[2 * r + 0];
            u64 A1 = s_c[2 * r + 1];

            #pragma unroll 1
            for (int j = 0; j < NJ; j++) {
                const int rj = 2 * r + j;
                const u64 c0 = s_coef[rj][0], c1 = s_coef[rj][1];
                const u64 c2 = s_coef[rj][2], c3 = s_coef[rj][3];

                u64 se = 0ULL, n0 = 0ULL, n1 = 0ULL;
                #pragma unroll
                for (int i = 0; i < NI; i++) {
                    const u64 t1 = fma2(c2, F0[i], c0);   // f0*(c0+c2*f0)
                    const u64 t2 = fma2(c3, F1[i], c1);   // + f1*(c1+c3*f1)
                    const u64 lg = fma2(F0[i], t1, mul2(F1[i], t2));
                    float llo, lhi; upk2(lg, llo, lhi);
                    const u64 e = pk2(ex2a(llo), ex2a(lhi));
                    se = add2(se, e);
                    n0 = fma2(e, F0[i], n0);
                    n1 = fma2(e, F1[i], n1);
                }

                float slo, shi; upk2(se, slo, shi);
                const u64 rinv = pk2(rcpa(slo), rcpa(shi));
                const u64 s0 = mul2(n0, rinv);
                const u64 s1 = mul2(n1, rinv);

                A0 = fma2(s_M[rj][0], s0, fma2(s_M[rj][1], s1, A0));
                A1 = fma2(s_M[rj][2], s0, fma2(s_M[rj][3], s1, A1));
            }

            float x0, x1, y0, y1;
            upk2(A0, x0, x1);
            upk2(A1, y0, y1);
            *reinterpret_cast<float2*>(out + base + r * 2)         = make_float2(x0, y0);
            *reinterpret_cast<float2*>(out + base + delta + r * 2) = make_float2(x1, y1);
        }
    }
}

extern "C" void kernel_launch(void* const* d_in, const int* in_sizes, int n_in,
                              void* d_out, int out_size) {
    const float* feat      = (const float*)d_in[0];
    const float* templates = (const float*)d_in[1];
    const float* gammas    = (const float*)d_in[2];
    const float* body_W    = (const float*)d_in[3];
    const float* body_b    = (const float*)d_in[4];
    const float* head_W    = (const float*)d_in[5];
    const float* head_b    = (const float*)d_in[6];
    float* out = (float*)d_out;

    const int B = in_sizes[0] / (NI * NL);
    const int half = B >> 1;

    // one resident wave: numSMs * 6 blocks (6 = lb occupancy at ~80 regs)
    static int blocks = 0;
    if (blocks == 0) {
        int sms = 0;
        cudaDeviceGetAttribute(&sms, cudaDevAttrMultiProcessorCount, 0);
        if (sms <= 0) sms = 148;
        blocks = sms * 6;
        const int maxb = (half + NT - 1) / NT;
        if (blocks > maxb) blocks = maxb;
    }
    abstraction_layer_kernel<<<blocks, NT>>>(
        feat, templates, gammas, body_W, body_b, head_W, head_b, out, B);
}

// round 15
// speedup vs baseline: 1.4329x; 1.3902x over previous
#include <cuda_runtime.h>

// AbstractionLayer: B=524288, I=12, R=6, J=2, L=2, V=4
// R15 = R8 (best macro-shape: 2 elems/thread lane-packed f32x2, features
// register-resident, one (r,j) per sweep, natural 80 regs, static 2048-CTA
// launch) + softmax reference-point trick: shift logits by lg_0 so e_0 = 1
// exactly -> skip one packed ex2 and the i=0 accumulation per (r,j).
// MUFU (the binding pipe: 2496 cyc/warp vs fma 2020) drops 7.7%.
// Softmax max-pass removed (logits bounded); log2e folded into coefs (raw
// ex2.approx); head*body pre-fused; rcp.approx (tol 1e-3).

#define NI 12
#define NR 6
#define NJ 2
#define NL 2
#define NV 4
#define NRJ 12
#define NT 128
#define LOG2E 1.4426950408889634f

typedef unsigned long long u64;

__device__ __forceinline__ u64 pk2(float lo, float hi) {
    u64 r; asm("mov.b64 %0, {%1,%2};" : "=l"(r) : "f"(lo), "f"(hi)); return r;
}
__device__ __forceinline__ void upk2(u64 v, float& lo, float& hi) {
    asm("mov.b64 {%0,%1}, %2;" : "=f"(lo), "=f"(hi) : "l"(v));
}
__device__ __forceinline__ u64 fma2(u64 a, u64 b, u64 c) {
    u64 d; asm("fma.rn.f32x2 %0, %1, %2, %3;" : "=l"(d) : "l"(a), "l"(b), "l"(c)); return d;
}
__device__ __forceinline__ u64 mul2(u64 a, u64 b) {
    u64 d; asm("mul.rn.f32x2 %0, %1, %2;" : "=l"(d) : "l"(a), "l"(b)); return d;
}
__device__ __forceinline__ u64 add2(u64 a, u64 b) {
    u64 d; asm("add.rn.f32x2 %0, %1, %2;" : "=l"(d) : "l"(a), "l"(b)); return d;
}
__device__ __forceinline__ float ex2a(float x) {
    float r; asm("ex2.approx.ftz.f32 %0, %1;" : "=f"(r) : "f"(x)); return r;
}
__device__ __forceinline__ float rcpa(float x) {
    float r; asm("rcp.approx.ftz.f32 %0, %1;" : "=f"(r) : "f"(x)); return r;
}

__global__ __launch_bounds__(NT, 6)
void abstraction_layer_kernel(
    const float* __restrict__ feat,       // [B, I, L]
    const float* __restrict__ templates,  // [R, J, L]
    const float* __restrict__ gammas,     // [R, J, L]
    const float* __restrict__ body_W,     // [R, J, V, L]
    const float* __restrict__ body_b,     // [R, J, V]
    const float* __restrict__ head_W,     // [R, L, V]
    const float* __restrict__ head_b,     // [R, L]
    float* __restrict__ out,              // [B, R, L]
    int B)
{
    __shared__ u64 s_coef[NRJ][4];       // log2e-scaled logit coefs, lane-dup
    __shared__ u64 s_M[NRJ][4];          // fused head*body, lane-dup
    __shared__ u64 s_c[NR * NL];         // fused bias, lane-dup

    const int tid = threadIdx.x;

    // ---- one-time parameter fusion (disjoint thread ranges) ----
    if (tid < NRJ) {
        const int r = tid >> 1, j = tid & 1;
        #pragma unroll
        for (int l = 0; l < NL; l++) {
            float g = gammas[(r * NJ + j) * NL + l];
            g = fminf(fmaxf(g, 0.0f), 1.0f);
            const float w = 1.0f - g;
            const float t = templates[(r * NJ + j) * NL + l];
            const float clin  = 2.0f * w * t * LOG2E;
            const float cquad = -w * LOG2E;
            s_coef[tid][l]     = pk2(clin, clin);
            s_coef[tid][2 + l] = pk2(cquad, cquad);
        }
    } else if (tid >= 16 && tid < 16 + 48) {
        const int idx = tid - 16;
        const int l2 = idx & 1, j = (idx >> 1) & 1, l = (idx >> 2) & 1, r = idx >> 3;
        float acc = 0.0f;
        #pragma unroll
        for (int v = 0; v < NV; v++)
            acc += head_W[(r * NL + l) * NV + v] *
                   body_W[((r * NJ + j) * NV + v) * NL + l2];
        s_M[r * NJ + j][l * 2 + l2] = pk2(acc, acc);
    } else if (tid >= 64 && tid < 64 + NR * NL) {
        const int idx = tid - 64;
        const int r = idx >> 1, l = idx & 1;
        float acc = head_b[r * NL + l];
        #pragma unroll
        for (int v = 0; v < NV; v++)
            acc += head_W[(r * NL + l) * NV + v] *
                   (body_b[(r * NJ + 0) * NV + v] + body_b[(r * NJ + 1) * NV + v]);
        s_c[idx] = pk2(acc, acc);
    }
    __syncthreads();

    const int half = B >> 1;
    const int t = blockIdx.x * blockDim.x + tid;
    if (t >= half) return;

    // ---- load features of elements (t, t+half) into REGISTERS, packed ----
    u64 F0[NI], F1[NI];
    {
        const float4* fa = reinterpret_cast<const float4*>(feat + (size_t)t * (NI * NL));
        const float4* fb = reinterpret_cast<const float4*>(feat + (size_t)(t + half) * (NI * NL));
        #pragma unroll
        for (int k = 0; k < 6; k++) {
            const float4 a = fa[k];
            const float4 b = fb[k];
            F0[2 * k]     = pk2(a.x, b.x); F1[2 * k]     = pk2(a.y, b.y);
            F0[2 * k + 1] = pk2(a.z, b.z); F1[2 * k + 1] = pk2(a.w, b.w);
        }
    }

    const size_t base  = (size_t)t * (NR * NL);
    const size_t delta = (size_t)half * (NR * NL);

    const u64 ONE2  = 0x3F8000003F800000ULL;   // {1.0f, 1.0f}
    const u64 NEG12 = 0xBF800000BF800000ULL;   // {-1.0f, -1.0f}

    // ---- 12 sweeps, one (r,j) each; features stay in registers ----
    #pragma unroll 1
    for (int r = 0; r < NR; r++) {
        u64 A0 = s_c[2 * r + 0];
        u64 A1 = s_c[2 * r + 1];

        #pragma unroll 1
        for (int j = 0; j < NJ; j++) {
            const int rj = 2 * r + j;
            const u64 c0 = s_coef[rj][0], c1 = s_coef[rj][1];
            const u64 c2 = s_coef[rj][2], c3 = s_coef[rj][3];

            // i = 0 is the softmax reference point: e_0 = 1 exactly.
            const u64 t01 = fma2(c2, F0[0], c0);
            const u64 t02 = fma2(c3, F1[0], c1);
            const u64 lg0 = fma2(F0[0], t01, mul2(F1[0], t02));

            u64 se = ONE2;
            u64 n0 = F0[0];
            u64 n1 = F1[0];

            #pragma unroll
            for (int i = 1; i < NI; i++) {
                const u64 t1 = fma2(c2, F0[i], c0);      // f0*(c0+c2*f0)
                const u64 t2 = fma2(c3, F1[i], c1);      // + f1*(c1+c3*f1)
                const u64 lg = fma2(F0[i], t1, mul2(F1[i], t2));
                const u64 d  = fma2(lg0, NEG12, lg);     // lg - lg0
                float dlo, dhi; upk2(d, dlo, dhi);
                const u64 e = pk2(ex2a(dlo), ex2a(dhi));
                se = add2(se, e);
                n0 = fma2(e, F0[i], n0);
                n1 = fma2(e, F1[i], n1);
            }

            float slo, shi; upk2(se, slo, shi);
            const u64 rinv = pk2(rcpa(slo), rcpa(shi));
            const u64 s0 = mul2(n0, rinv);
            const u64 s1 = mul2(n1, rinv);

            A0 = fma2(s_M[rj][0], s0, fma2(s_M[rj][1], s1, A0));
            A1 = fma2(s_M[rj][2], s0, fma2(s_M[rj][3], s1, A1));
        }

        float x0, x1, y0, y1;
        upk2(A0, x0, x1);
        upk2(A1, y0, y1);
        *reinterpret_cast<float2*>(out + base + r * 2)         = make_float2(x0, y0);
        *reinterpret_cast<float2*>(out + base + delta + r * 2) = make_float2(x1, y1);
    }
}

extern "C" void kernel_launch(void* const* d_in, const int* in_sizes, int n_in,
                              void* d_out, int out_size) {
    const float* feat      = (const float*)d_in[0];
    const float* templates = (const float*)d_in[1];
    const float* gammas    = (const float*)d_in[2];
    const float* body_W    = (const float*)d_in[3];
    const float* body_b    = (const float*)d_in[4];
    const float* head_W    = (const float*)d_in[5];
    const float* head_b    = (const float*)d_in[6];
    float* out = (float*)d_out;

    const int B = in_sizes[0] / (NI * NL);
    const int half = B >> 1;
    const int blocks = (half + NT - 1) / NT;
    abstraction_layer_kernel<<<blocks, NT>>>(
        feat, templates, gammas, body_W, body_b, head_W, head_b, out, B);
}